// round 3
// baseline (speedup 1.0000x reference)
#include <cuda_runtime.h>

#define NB 256
#define NT 96
#define ND 32
#define NH 128
#define NOUT 32
#define NF 24
#define BC 64
#define NCTA 128
#define NTHR 512

#define HS2 129   // ull stride for hdup rows (padded)
#define GSS 130   // float stride for gs rows (padded)

#define F_OFS 0
#define F_CNT (NB*NF*NOUT)
#define A_OFS F_CNT
#define A_CNT (NB*NT*ND)
#define B_OFS (A_OFS + A_CNT)
#define B_CNT (NB*NF*ND)
#define O_OFS (B_OFS + B_CNT)

typedef unsigned long long ull;

// ------------- scratch (no allocs allowed) -------------
__device__ float g_h[ND*NB*NH];
__device__ float g_c[ND*NB*NH];
__device__ float g_gn[ND*NB*NH];
__device__ float g_den[NB*ND];
__device__ float g_mu[NB*ND*NOUT];
__device__ float g_bt[NB*ND];

struct EncSmem {
    ull   hdup[BC*HS2];   // h duplicated into both f32x2 lanes, padded rows
    float gs[BC*GSS];     // g_n staging, padded rows
    float Fa_s[NH];
    float xs[BC];
    float es[BC];
    float den_s[BC];
};

// ------------- packed f32x2 helpers -------------
__device__ __forceinline__ ull pack2(float lo, float hi) {
    ull r;
    asm("mov.b64 %0, {%1, %2};" : "=l"(r)
        : "r"(__float_as_uint(lo)), "r"(__float_as_uint(hi)));
    return r;
}
__device__ __forceinline__ ull dup2(float v) {
    ull r; unsigned u = __float_as_uint(v);
    asm("mov.b64 %0, {%1, %1};" : "=l"(r) : "r"(u));
    return r;
}
__device__ __forceinline__ void unpack2(ull p, float &lo, float &hi) {
    unsigned a, b;
    asm("mov.b64 {%0, %1}, %2;" : "=r"(a), "=r"(b) : "l"(p));
    lo = __uint_as_float(a); hi = __uint_as_float(b);
}
__device__ __forceinline__ void fma2(ull &acc, ull a, ull b) {
    asm("fma.rn.f32x2 %0, %1, %2, %0;" : "+l"(acc) : "l"(a), "l"(b));
}

__device__ __forceinline__ float sigf(float x) {
    return __fdividef(1.f, 1.f + __expf(-x));
}
__device__ __forceinline__ float tanhfast(float x) {
    float e = __expf(-2.f * x);
    return __fdividef(1.f - e, 1.f + e);
}

// ------------- one gate GEMM -------------
// thread: rows b0t..b0t+1, cols hk0..hk0+7. acc[bi*4+p] = cols (hk0+2p, hk0+2p+1).
__device__ __forceinline__ void gate_gemm(
    const float* __restrict__ Wd, const float* __restrict__ Ud,
    const float* __restrict__ bd, const ull* __restrict__ hd,
    const float* __restrict__ xs, int hk0, int b0t, ull acc[8])
{
    float4 u0 = *(const float4*)(Ud + hk0);
    float4 u1 = *(const float4*)(Ud + hk0 + 4);
    float4 v0 = *(const float4*)(bd + hk0);
    float4 v1 = *(const float4*)(bd + hk0 + 4);
#pragma unroll
    for (int bi = 0; bi < 2; ++bi) {
        float xv = xs[b0t + bi];
        acc[bi*4+0] = pack2(fmaf(xv,u0.x,v0.x), fmaf(xv,u0.y,v0.y));
        acc[bi*4+1] = pack2(fmaf(xv,u0.z,v0.z), fmaf(xv,u0.w,v0.w));
        acc[bi*4+2] = pack2(fmaf(xv,u1.x,v1.x), fmaf(xv,u1.y,v1.y));
        acc[bi*4+3] = pack2(fmaf(xv,u1.z,v1.z), fmaf(xv,u1.w,v1.w));
    }
    const float* wp = Wd + hk0;
    const ull* h0p = hd + (size_t)b0t * HS2;
    const ull* h1p = hd + (size_t)(b0t + 1) * HS2;
#pragma unroll 4
    for (int k = 0; k < NH; ++k) {
        ulonglong2 w01 = *(const ulonglong2*)(wp);
        ulonglong2 w23 = *(const ulonglong2*)(wp + 4);
        wp += NH;
        ull h0 = h0p[k], h1 = h1p[k];
        fma2(acc[0], h0, w01.x);
        fma2(acc[1], h0, w01.y);
        fma2(acc[2], h0, w23.x);
        fma2(acc[3], h0, w23.y);
        fma2(acc[4], h1, w01.x);
        fma2(acc[5], h1, w01.y);
        fma2(acc[6], h1, w23.x);
        fma2(acc[7], h1, w23.y);
    }
}

// ------------- full LSTM cell for this thread's 16 elements -------------
__device__ __forceinline__ void cell_step(
    const float* __restrict__ Wjd, const float* __restrict__ Wid,
    const float* __restrict__ Wfd, const float* __restrict__ Wod,
    const float* __restrict__ Ujd, const float* __restrict__ Uid,
    const float* __restrict__ Ufd, const float* __restrict__ Uod,
    const float* __restrict__ bjd, const float* __restrict__ bid,
    const float* __restrict__ bfd, const float* __restrict__ bod,
    const ull* __restrict__ hd, const float* __restrict__ xs,
    int hk0, int b0t, float* c, float* h2)
{
    ull acc[8];
    gate_gemm(Wjd, Ujd, bjd, hd, xs, hk0, b0t, acc);     // j
#pragma unroll
    for (int e = 0; e < 8; ++e) {
        float lo, hi; unpack2(acc[e], lo, hi);
        int ii = (e >> 2) * 8 + (e & 3) * 2;
        h2[ii] = tanhfast(lo); h2[ii+1] = tanhfast(hi);
    }
    gate_gemm(Wid, Uid, bid, hd, xs, hk0, b0t, acc);     // i  (h2 <- i*j)
#pragma unroll
    for (int e = 0; e < 8; ++e) {
        float lo, hi; unpack2(acc[e], lo, hi);
        int ii = (e >> 2) * 8 + (e & 3) * 2;
        h2[ii] *= sigf(lo); h2[ii+1] *= sigf(hi);
    }
    gate_gemm(Wfd, Ufd, bfd, hd, xs, hk0, b0t, acc);     // f  (c <- c*f + i*j)
#pragma unroll
    for (int e = 0; e < 8; ++e) {
        float lo, hi; unpack2(acc[e], lo, hi);
        int ii = (e >> 2) * 8 + (e & 3) * 2;
        c[ii]   = fmaf(c[ii],   sigf(lo), h2[ii]);
        c[ii+1] = fmaf(c[ii+1], sigf(hi), h2[ii+1]);
    }
    gate_gemm(Wod, Uod, bod, hd, xs, hk0, b0t, acc);     // o  (h2 <- o*tanh(c))
#pragma unroll
    for (int e = 0; e < 8; ++e) {
        float lo, hi; unpack2(acc[e], lo, hi);
        int ii = (e >> 2) * 8 + (e & 3) * 2;
        h2[ii]   = sigf(lo) * tanhfast(c[ii]);
        h2[ii+1] = sigf(hi) * tanhfast(c[ii+1]);
    }
}

// ------------- mu / bt for next fc step (hdup = h, gs = g_n) -------------
__device__ __forceinline__ void compute_mu_bt(
    EncSmem* s, int d, int b0, int tid,
    const float* __restrict__ Phi_w, const float* __restrict__ Phi_b,
    const float* __restrict__ Fbw, const float* __restrict__ Fbb)
{
    int outc = tid & 31;
    int bg = tid >> 5;                      // 16 groups x 4 batch rows
    float acc[4];
    float pb = Phi_b[outc];
#pragma unroll
    for (int r = 0; r < 4; ++r) acc[r] = pb;
#pragma unroll 2
    for (int k = 0; k < NH; ++k) {
        float pg = Phi_w[k*NOUT + outc];
        float ph = Phi_w[(NH + k)*NOUT + outc];
#pragma unroll
        for (int r = 0; r < 4; ++r) {
            int b = bg*4 + r;
            float hv = *(const float*)&s->hdup[b*HS2 + k];   // low lane = h
            acc[r] = fmaf(s->gs[b*GSS + k], pg, acc[r]);
            acc[r] = fmaf(hv, ph, acc[r]);
        }
    }
#pragma unroll
    for (int r = 0; r < 4; ++r)
        g_mu[(((size_t)(b0 + bg*4 + r))*ND + d)*NOUT + outc] = acc[r];

    if (tid < BC) {
        int b = tid;
        float a0 = 0.f, a1 = 0.f;
#pragma unroll 2
        for (int k = 0; k < NH; k += 2) {
            float hv0 = *(const float*)&s->hdup[b*HS2 + k];
            float hv1 = *(const float*)&s->hdup[b*HS2 + k + 1];
            a0 = fmaf(s->gs[b*GSS + k],     Fbw[k],        a0);
            a0 = fmaf(hv0,                  Fbw[NH + k],   a0);
            a1 = fmaf(s->gs[b*GSS + k + 1], Fbw[k+1],      a1);
            a1 = fmaf(hv1,                  Fbw[NH + k+1], a1);
        }
        g_bt[(size_t)(b0 + b)*ND + d] = __expf(tanhfast(a0 + a1 + Fbb[0]));
    }
}

// ================= encoder: 96 steps persistent =================
__global__ void __launch_bounds__(NTHR, 1) enc_kernel(
    const float* __restrict__ x,
    const float* __restrict__ Uj, const float* __restrict__ Ui,
    const float* __restrict__ Uf, const float* __restrict__ Uo,
    const float* __restrict__ Wj, const float* __restrict__ Wi,
    const float* __restrict__ Wf, const float* __restrict__ Wo,
    const float* __restrict__ bj, const float* __restrict__ bi_,
    const float* __restrict__ bf, const float* __restrict__ bo,
    const float* __restrict__ Fa, const float* __restrict__ Fab,
    const float* __restrict__ Phi_w, const float* __restrict__ Phi_b,
    const float* __restrict__ Fbw, const float* __restrict__ Fbb,
    float* __restrict__ out)
{
    extern __shared__ char smem_raw[];
    EncSmem* s = (EncSmem*)smem_raw;

    const int tid = threadIdx.x;
    const int d  = blockIdx.x >> 2;
    const int b0 = (blockIdx.x & 3) * BC;
    const int hk0 = (tid & 15) * 8;
    const int b0t = (tid >> 4) * 2;

    const size_t dHH = (size_t)d * NH * NH;
    const float *Wjd = Wj + dHH, *Wid = Wi + dHH, *Wfd = Wf + dHH, *Wod = Wo + dHH;
    const float *Ujd = Uj + d*NH, *Uid = Ui + d*NH, *Ufd = Uf + d*NH, *Uod = Uo + d*NH;
    const float *bjd = bj + d*NH, *bid = bi_ + d*NH, *bfd = bf + d*NH, *bod = bo + d*NH;
    const float fab = Fab[d];

    for (int i = tid; i < BC*HS2; i += NTHR) s->hdup[i] = 0ull;
    if (tid < BC) s->den_s[tid] = 0.f;
    if (tid < NH) s->Fa_s[tid] = Fa[d*NH + tid];

    float c[16], num[16], h2[16];
#pragma unroll
    for (int i = 0; i < 16; ++i) { c[i] = 0.f; num[i] = 0.f; }
    __syncthreads();

    for (int t = 0; t < NT; ++t) {
        if (tid < BC) s->xs[tid] = x[((size_t)(b0 + tid)*NT + t)*ND + d];
        __syncthreads();

        cell_step(Wjd,Wid,Wfd,Wod, Ujd,Uid,Ufd,Uod, bjd,bid,bfd,bod,
                  s->hdup, s->xs, hk0, b0t, c, h2);
        __syncthreads();                      // gemm reads of old h done

#pragma unroll
        for (int bb = 0; bb < 2; ++bb) {
            int b = b0t + bb;
#pragma unroll
            for (int cc = 0; cc < 8; ++cc)
                s->hdup[b*HS2 + hk0 + cc] = dup2(h2[bb*8 + cc]);
            size_t off = O_OFS + (((size_t)(b0 + b)*NT + t)*ND + d)*NH + hk0;
            *(float4*)(out + off)     = make_float4(h2[bb*8+0],h2[bb*8+1],h2[bb*8+2],h2[bb*8+3]);
            *(float4*)(out + off + 4) = make_float4(h2[bb*8+4],h2[bb*8+5],h2[bb*8+6],h2[bb*8+7]);
        }
        __syncthreads();                      // new h visible

        if (tid < BC) {
            const float* hrow = (const float*)&s->hdup[tid*HS2];
            float s0 = 0.f, s1 = 0.f;
#pragma unroll 4
            for (int k = 0; k < NH; k += 2) {
                s0 = fmaf(hrow[2*k],     s->Fa_s[k],   s0);
                s1 = fmaf(hrow[2*(k+1)], s->Fa_s[k+1], s1);
            }
            float e = __expf(tanhfast(s0 + s1 + fab));
            s->es[tid] = e;
            s->den_s[tid] += e;
            out[A_OFS + ((size_t)(b0 + tid)*NT + t)*ND + d] = e;  // normalized later
        }
        __syncthreads();                      // es visible

#pragma unroll
        for (int bb = 0; bb < 2; ++bb) {
            float e = s->es[b0t + bb];
#pragma unroll
            for (int cc = 0; cc < 8; ++cc)
                num[bb*8+cc] = fmaf(e, h2[bb*8+cc], num[bb*8+cc]);
        }
    }

    // epilogue: g_n, den, h, c; then mu/bt for fc step 0
#pragma unroll
    for (int bb = 0; bb < 2; ++bb) {
        int b = b0t + bb;
        float inv = __fdividef(1.f, s->den_s[b]);
        size_t gofs = ((size_t)d*NB + b0 + b)*NH + hk0;
#pragma unroll
        for (int cc = 0; cc < 8; ++cc) {
            float gn = num[bb*8+cc] * inv;
            s->gs[b*GSS + hk0 + cc] = gn;
            g_gn[gofs + cc] = gn;
            g_h[gofs + cc] = h2[bb*8+cc];
            g_c[gofs + cc] = c[bb*8+cc];
        }
    }
    if (tid < BC) g_den[(size_t)(b0 + tid)*ND + d] = s->den_s[tid];
    __syncthreads();

    compute_mu_bt(s, d, b0, tid, Phi_w, Phi_b, Fbw, Fbb);
}

// ================= alphas finalize =================
__global__ void alphas_fin_kernel(float* __restrict__ out) {
    int i = blockIdx.x * 256 + threadIdx.x;
    if (i >= A_CNT) return;
    int b = i / (NT*ND);
    int d = i & (ND-1);
    out[A_OFS + i] = __fdividef(out[A_OFS + i], g_den[(size_t)b*ND + d]);
}

// ================= fc step: fold reduce + cell + mu/bt =================
__global__ void __launch_bounds__(NTHR, 1) cellmu_kernel(
    int f, int last,
    const float* __restrict__ Uj, const float* __restrict__ Ui,
    const float* __restrict__ Uf, const float* __restrict__ Uo,
    const float* __restrict__ Wj, const float* __restrict__ Wi,
    const float* __restrict__ Wf, const float* __restrict__ Wo,
    const float* __restrict__ bj, const float* __restrict__ bi_,
    const float* __restrict__ bf, const float* __restrict__ bo,
    const float* __restrict__ Phi_w, const float* __restrict__ Phi_b,
    const float* __restrict__ Fbw, const float* __restrict__ Fbb,
    const float* __restrict__ proj_w, const float* __restrict__ proj_b,
    float* __restrict__ out)
{
    extern __shared__ char smem_raw[];
    EncSmem* s = (EncSmem*)smem_raw;

    const int tid = threadIdx.x;
    const int d  = blockIdx.x >> 2;
    const int b0 = (blockIdx.x & 3) * BC;
    const int hk0 = (tid & 15) * 8;
    const int b0t = (tid >> 4) * 2;
    const int lane = tid & 31;
    const int w = tid >> 5;

    // ---- phase 0: softmax over D, y, forecasts, betas, prev (-> xs) ----
    {
#pragma unroll
        for (int r = 0; r < 4; ++r) {
            int b = w*4 + r;
            float bt = g_bt[(size_t)(b0 + b)*ND + lane];
            float ssum = bt;
#pragma unroll
            for (int o = 16; o > 0; o >>= 1)
                ssum += __shfl_xor_sync(0xffffffffu, ssum, o);
            float beta = __fdividef(bt, ssum);
            out[B_OFS + ((size_t)(b0 + b)*NF + f)*ND + lane] = beta;

            float y = 0.f;
            const float* mup = g_mu + ((size_t)(b0 + b)*ND)*NOUT + lane;
#pragma unroll
            for (int d2 = 0; d2 < ND; ++d2)
                y = fmaf(__shfl_sync(0xffffffffu, beta, d2), mup[d2*NOUT], y);
            out[F_OFS + ((size_t)(b0 + b)*NF + f)*NOUT + lane] = y;

            float p = y * proj_w[lane*ND + d];
#pragma unroll
            for (int o = 16; o > 0; o >>= 1)
                p += __shfl_xor_sync(0xffffffffu, p, o);
            if (lane == 0) s->xs[b] = p + proj_b[d];
        }
    }
    if (last) return;

    // ---- load state into smem in parallel with phase 0's tail ----
    for (int i = tid; i < BC*NH; i += NTHR) {
        int b = i >> 7, k = i & 127;
        size_t gofs = ((size_t)d*NB + b0 + b)*NH + k;
        s->hdup[b*HS2 + k] = dup2(g_h[gofs]);
        s->gs[b*GSS + k]   = g_gn[gofs];
    }

    float c[16], h2[16];
#pragma unroll
    for (int bb = 0; bb < 2; ++bb) {
        size_t gofs = ((size_t)d*NB + b0 + b0t + bb)*NH + hk0;
        float4 c0 = *(const float4*)(g_c + gofs);
        float4 c1 = *(const float4*)(g_c + gofs + 4);
        c[bb*8+0]=c0.x; c[bb*8+1]=c0.y; c[bb*8+2]=c0.z; c[bb*8+3]=c0.w;
        c[bb*8+4]=c1.x; c[bb*8+5]=c1.y; c[bb*8+6]=c1.z; c[bb*8+7]=c1.w;
    }
    __syncthreads();

    const size_t dHH = (size_t)d * NH * NH;
    const float *Wjd = Wj + dHH, *Wid = Wi + dHH, *Wfd = Wf + dHH, *Wod = Wo + dHH;
    const float *Ujd = Uj + d*NH, *Uid = Ui + d*NH, *Ufd = Uf + d*NH, *Uod = Uo + d*NH;
    const float *bjd = bj + d*NH, *bid = bi_ + d*NH, *bfd = bf + d*NH, *bod = bo + d*NH;

    cell_step(Wjd,Wid,Wfd,Wod, Ujd,Uid,Ufd,Uod, bjd,bid,bfd,bod,
              s->hdup, s->xs, hk0, b0t, c, h2);
    __syncthreads();

#pragma unroll
    for (int bb = 0; bb < 2; ++bb) {
        int b = b0t + bb;
        size_t gofs = ((size_t)d*NB + b0 + b)*NH + hk0;
#pragma unroll
        for (int cc = 0; cc < 8; ++cc) {
            s->hdup[b*HS2 + hk0 + cc] = dup2(h2[bb*8+cc]);
            g_h[gofs + cc] = h2[bb*8+cc];
            g_c[gofs + cc] = c[bb*8+cc];
        }
    }
    __syncthreads();

    compute_mu_bt(s, d, b0, tid, Phi_w, Phi_b, Fbw, Fbb);
}

// ================= launch =================
extern "C" void kernel_launch(void* const* d_in, const int* in_sizes, int n_in,
                              void* d_out, int out_size) {
    const float* x    = (const float*)d_in[0];
    const float* Uj   = (const float*)d_in[1];
    const float* Ui   = (const float*)d_in[2];
    const float* Uf   = (const float*)d_in[3];
    const float* Uo   = (const float*)d_in[4];
    const float* Wj   = (const float*)d_in[5];
    const float* Wi   = (const float*)d_in[6];
    const float* Wf   = (const float*)d_in[7];
    const float* Wo   = (const float*)d_in[8];
    const float* bj   = (const float*)d_in[9];
    const float* bi   = (const float*)d_in[10];
    const float* bf   = (const float*)d_in[11];
    const float* bo   = (const float*)d_in[12];
    const float* Fa   = (const float*)d_in[13];
    const float* Fab  = (const float*)d_in[14];
    const float* Fbw  = (const float*)d_in[15];
    const float* Fbb  = (const float*)d_in[16];
    const float* Phw  = (const float*)d_in[17];
    const float* Phb  = (const float*)d_in[18];
    const float* prw  = (const float*)d_in[19];
    const float* prb  = (const float*)d_in[20];
    float* out = (float*)d_out;

    int smem = (int)sizeof(EncSmem);
    cudaFuncSetAttribute(enc_kernel,    cudaFuncAttributeMaxDynamicSharedMemorySize, smem);
    cudaFuncSetAttribute(cellmu_kernel, cudaFuncAttributeMaxDynamicSharedMemorySize, smem);

    enc_kernel<<<NCTA, NTHR, smem>>>(x, Uj,Ui,Uf,Uo, Wj,Wi,Wf,Wo, bj,bi,bf,bo,
                                     Fa, Fab, Phw, Phb, Fbw, Fbb, out);
    alphas_fin_kernel<<<(A_CNT + 255)/256, 256>>>(out);

    for (int f = 0; f < NF; ++f) {
        cellmu_kernel<<<NCTA, NTHR, smem>>>(f, (f == NF-1) ? 1 : 0,
                                            Uj,Ui,Uf,Uo, Wj,Wi,Wf,Wo,
                                            bj,bi,bf,bo, Phw, Phb, Fbw, Fbb,
                                            prw, prb, out);
    }
}